// round 11
// baseline (speedup 1.0000x reference)
#include <cuda_runtime.h>
#include <cstdint>

// ============================================================================
// Problem shapes (fixed by reference setup_inputs)
// ============================================================================
#define BATCH      4
#define NPTS       8192
#define L_DIFF     98304       // 4*8192*3
#define L_STYLE    2048        // 4*512
#define L_CONTENT  1048576     // 4*1024*256
#define L_ID       98304

// bucketing
#define NB         256
#define XMIN       (-5.12f)
#define BW         0.04f
#define INV_BW     25.0f
#define W_PAD      6           // +-0.24 window pad; tail handled by expansion

// kernel 1: 8 build blocks + 104 MSE blocks
#define K1_THREADS 256
#define BUILD_BLKS 8
#define MSE_BLKS   104
#define K1_BLOCKS  (BUILD_BLKS + MSE_BLKS)

// kernel 2: 512 blocks x 128 threads; 1 query/thread, 128 sorted queries/block
#define K2_THREADS 128
#define K2_BLOCKS  512
#define TILE_PAIRS 256         // 512 candidates staged per tile

// ============================================================================
// Scratch (device globals; no allocation allowed).
// g_sorted / g_bstart fully overwritten every call by kernel 1.
// g_acc / g_cham / g_ctr: zero-init == clean; kernel 2's last block resets
// them every call -> deterministic replays, no init launch.
// ============================================================================
__device__ float4 g_sorted[8][NPTS];    // [cloud*4+b]; cloud 0 = x_original, 1 = x_cycle
__device__ int    g_bstart[8][NB + 1];  // bucket prefix offsets
__device__ double g_acc[4];             // diff, style, content, identity sums
__device__ double g_cham;               // sum of sqrt(min d2)
__device__ unsigned int g_ctr;          // last-block ticket (auto-wrap)

static __device__ __forceinline__ int bucket_of(float x) {
    int k = (int)((x - XMIN) * INV_BW);
    return k < 0 ? 0 : (k > NB - 1 ? NB - 1 : k);
}

// packed f32x2 helpers (Blackwell; PTX-only)
static __device__ __forceinline__ unsigned long long pk2(float lo, float hi) {
    unsigned long long r;
    asm("mov.b64 %0, {%1, %2};" : "=l"(r) : "f"(lo), "f"(hi));
    return r;
}
static __device__ __forceinline__ void upk2(unsigned long long v, float& lo, float& hi) {
    asm("mov.b64 {%0, %1}, %2;" : "=f"(lo), "=f"(hi) : "l"(v));
}
static __device__ __forceinline__ unsigned long long fma2(unsigned long long a,
                                                          unsigned long long b,
                                                          unsigned long long c) {
    unsigned long long d;
    asm("fma.rn.f32x2 %0, %1, %2, %3;" : "=l"(d) : "l"(a), "l"(b), "l"(c));
    return d;
}
static __device__ __forceinline__ unsigned long long mul2(unsigned long long a,
                                                          unsigned long long b) {
    unsigned long long d;
    asm("mul.rn.f32x2 %0, %1, %2;" : "=l"(d) : "l"(a), "l"(b));
    return d;
}
static __device__ __forceinline__ unsigned long long add2(unsigned long long a,
                                                          unsigned long long b) {
    unsigned long long d;
    asm("add.rn.f32x2 %0, %1, %2;" : "=l"(d) : "l"(a), "l"(b));
    return d;
}

// ============================================================================
// Kernel 1, blocks [0,8): bucket-sort one cloud (by x) + parallel prefix.
// In-bucket order is atomic-order (nondeterministic) — harmless: consumers
// reduce with min/mean (order-independent up to ~1e-7 float jitter).
// ============================================================================
static __device__ __forceinline__ void build_cloud(
    int id, const float* __restrict__ xo, const float* __restrict__ xc,
    int* hist, int* pos) {

    const int cloud = id >> 2;
    const int b     = id & 3;
    const float* src = (cloud ? xc : xo) + (size_t)b * NPTS * 3;
    const int t = threadIdx.x;

    if (t < NB) hist[t] = 0;
    __syncthreads();

    for (int i = t; i < NPTS; i += K1_THREADS)
        atomicAdd(&hist[bucket_of(src[3 * i])], 1);
    __syncthreads();

    // parallel inclusive scan (Hillis-Steele, 8 steps, 256 threads)
    int mine = (t < NB) ? hist[t] : 0;
    for (int off = 1; off < NB; off <<= 1) {
        int u = (t < NB && t >= off) ? hist[t - off] : 0;
        __syncthreads();
        if (t < NB) hist[t] += u;
        __syncthreads();
    }
    if (t < NB) {
        int excl = hist[t] - mine;     // exclusive prefix
        g_bstart[id][t] = excl;
        pos[t] = excl;
    }
    if (t == 0) g_bstart[id][NB] = NPTS;
    __syncthreads();

    for (int i = t; i < NPTS; i += K1_THREADS) {
        float x = src[3 * i], y = src[3 * i + 1], z = src[3 * i + 2];
        int k = bucket_of(x);
        int p = atomicAdd(&pos[k], 1);
        g_sorted[id][p] = make_float4(x, y, z, 0.0f);
    }
}

// ============================================================================
// Kernel 1, blocks [8,112): all 4 MSE sums, float4-vectorized -> g_acc.
// ============================================================================
static __device__ __forceinline__ float mse_part_v4(const float4* __restrict__ a,
                                                    const float4* __restrict__ b,
                                                    int n4, int gid, int stride) {
    float s = 0.f;
    for (int i = gid; i < n4; i += stride) {
        float4 va = a[i], vb = b[i];
        float d0 = va.x - vb.x, d1 = va.y - vb.y, d2 = va.z - vb.z, d3 = va.w - vb.w;
        s += d0 * d0 + d1 * d1 + d2 * d2 + d3 * d3;
    }
    return s;
}

static __device__ __forceinline__ void mse_part(
    int m, const float* pred, const float* targ, const float* ssim,
    const float* sreal, const float* corg, const float* cgen,
    const float* xorg, const float* xid, float* sm) {

    const int gid    = m * K1_THREADS + threadIdx.x;
    const int stride = MSE_BLKS * K1_THREADS;

    float s[4];
    s[0] = mse_part_v4((const float4*)pred, (const float4*)targ,  L_DIFF / 4,    gid, stride);
    s[1] = mse_part_v4((const float4*)ssim, (const float4*)sreal, L_STYLE / 4,   gid, stride);
    s[2] = mse_part_v4((const float4*)corg, (const float4*)cgen,  L_CONTENT / 4, gid, stride);
    s[3] = mse_part_v4((const float4*)xorg, (const float4*)xid,   L_ID / 4,      gid, stride);

    if (threadIdx.x < 4) sm[threadIdx.x] = 0.f;
    __syncthreads();
#pragma unroll
    for (int k = 0; k < 4; k++) {
#pragma unroll
        for (int off = 16; off > 0; off >>= 1)
            s[k] += __shfl_down_sync(0xFFFFFFFFu, s[k], off);
        if ((threadIdx.x & 31) == 0) atomicAdd(&sm[k], s[k]);
    }
    __syncthreads();
    if (threadIdx.x < 4) atomicAdd(&g_acc[threadIdx.x], (double)sm[threadIdx.x]);
}

__global__ void __launch_bounds__(K1_THREADS)
build_mse_kernel(const float* __restrict__ xo,   const float* __restrict__ xc,
                 const float* __restrict__ pred, const float* __restrict__ targ,
                 const float* __restrict__ ssim, const float* __restrict__ sreal,
                 const float* __restrict__ corg, const float* __restrict__ cgen,
                 const float* __restrict__ xid) {
    __shared__ int   hist[NB];
    __shared__ int   pos[NB];
    __shared__ float sm[4];
    const int bid = blockIdx.x;
    if (bid < BUILD_BLKS) {
        build_cloud(bid, xo, xc, hist, pos);
    } else {
        mse_part(bid - BUILD_BLKS, pred, targ, ssim, sreal, corg, cgen, xo, xid, sm);
    }
}

// ============================================================================
// Kernel 2: pruned-window NN with the DENSE compute engine.
// Block = 128 consecutive sorted queries. Window = [bucket(qmin)-W,
// bucket(qmax)+W] = one contiguous candidate range, staged through shared in
// packed-f32x2 tiles; inner loop identical to the proven dense kernel
// (2xLDS.128 + mul2/fma2/fma2/add2 + unpack + 2 FMNMX per 2 candidates,
// two independent min chains). Tail exactness: warp-uniform edge-bound
// expansion over extra buckets (rare; tail warps only).
// ============================================================================
__global__ void __launch_bounds__(K2_THREADS)
query_kernel(float* __restrict__ out, int out_size) {
    __shared__ __align__(16) unsigned long long t_ab[2 * TILE_PAIRS];
    __shared__ __align__(16) unsigned long long t_cd[2 * TILE_PAIRS];
    __shared__ float warpsum[K2_THREADS / 32];
    __shared__ bool  s_last;

    const int tid  = threadIdx.x;
    const int lane = tid & 31;
    const int wid  = tid >> 5;
    const unsigned FULL = 0xFFFFFFFFu;

    const int gb    = blockIdx.x;        // 0..511
    const int dir   = gb >> 8;           // 0: queries=xo, cands=xc ; 1: swapped
    const int b     = (gb >> 6) & 3;
    const int chunk = gb & 63;           // 64 chunks of 128 queries
    const int qc = dir ? 1 : 0;
    const int cc = 1 - qc;

    const float4* __restrict__ Q   = g_sorted[qc * 4 + b] + chunk * K2_THREADS;
    const float4* __restrict__ C   = g_sorted[cc * 4 + b];
    const int*    __restrict__ bst = g_bstart[cc * 4 + b];

    const float4 q = Q[tid];
    // block window from sorted extremes (broadcast loads)
    int l = bucket_of(Q[0].x) - W_PAD;              if (l < 0) l = 0;
    int r = bucket_of(Q[K2_THREADS - 1].x) + W_PAD; if (r > NB - 1) r = NB - 1;
    const int s0 = bst[l], e0 = bst[r + 1];

    const unsigned long long nx = pk2(-2.0f * q.x, -2.0f * q.x);
    const unsigned long long ny = pk2(-2.0f * q.y, -2.0f * q.y);
    const unsigned long long nz = pk2(-2.0f * q.z, -2.0f * q.z);
    const float rsq = q.x * q.x + q.y * q.y + q.z * q.z;

    float minL = 3.4e38f, minH = 3.4e38f;

    for (int base = s0; base < e0; base += 2 * TILE_PAIRS) {
        // stage up to 512 candidates, packed: ab={x,x'},{y,y'}; cd={z,z'},{q,q'}
        for (int p = tid; p < TILE_PAIRS; p += K2_THREADS) {
            int i0 = base + 2 * p, i1 = i0 + 1;
            float4 c0 = (i0 < e0) ? C[i0] : make_float4(1e6f, 1e6f, 1e6f, 0.f);
            float4 c1 = (i1 < e0) ? C[i1] : make_float4(1e6f, 1e6f, 1e6f, 0.f);
            t_ab[2 * p]     = pk2(c0.x, c1.x);
            t_ab[2 * p + 1] = pk2(c0.y, c1.y);
            t_cd[2 * p]     = pk2(c0.z, c1.z);
            t_cd[2 * p + 1] = pk2(c0.x * c0.x + c0.y * c0.y + c0.z * c0.z,
                                  c1.x * c1.x + c1.y * c1.y + c1.z * c1.z);
        }
        __syncthreads();

#pragma unroll 8
        for (int p = 0; p < TILE_PAIRS; p++) {
            ulonglong2 v1 = *(const ulonglong2*)(t_ab + 2 * p);  // x, y
            ulonglong2 v2 = *(const ulonglong2*)(t_cd + 2 * p);  // z, |c|^2
            unsigned long long sacc = mul2(nx, v1.x);
            sacc = fma2(ny, v1.y, sacc);
            sacc = fma2(nz, v2.x, sacc);
            unsigned long long term = add2(sacc, v2.y);  // |c|^2 - 2 q.c
            float lo, hi;
            upk2(term, lo, hi);
            minL = fminf(minL, lo);      // independent chains
            minH = fminf(minH, hi);
        }
        __syncthreads();
    }

    float best = fmaxf(rsq + fminf(minL, minH), 0.0f);  // clamp like reference

    // warp-uniform expansion for queries whose window may be insufficient
    while (true) {
        float dl = q.x - (XMIN + l * BW);           // dist to right edge of bucket l-1
        float dr = (XMIN + (r + 1) * BW) - q.x;     // dist to left edge of bucket r+1
        dl = fmaxf(dl - 1e-4f, 0.0f);               // eps pad: keep underestimate
        dr = fmaxf(dr - 1e-4f, 0.0f);
        unsigned vl = __ballot_sync(FULL, dl * dl < best);
        unsigned vr = __ballot_sync(FULL, dr * dr < best);
        bool aL = (l > 0)      && (vl != 0u);
        bool aR = (r < NB - 1) && (vr != 0u);
        if (!aL && !aR) break;
        if (aL) {
            l--;
            for (int i = bst[l]; i < bst[l + 1]; i++) {
                float4 c = C[i];
                float dx = q.x - c.x, dy = q.y - c.y, dz = q.z - c.z;
                best = fminf(best, fmaf(dx, dx, fmaf(dy, dy, dz * dz)));
            }
        }
        if (aR) {
            r++;
            for (int i = bst[r]; i < bst[r + 1]; i++) {
                float4 c = C[i];
                float dx = q.x - c.x, dy = q.y - c.y, dz = q.z - c.z;
                best = fminf(best, fmaf(dx, dx, fmaf(dy, dy, dz * dz)));
            }
        }
    }

    float contrib = sqrtf(best);

    // block reduction -> g_cham
#pragma unroll
    for (int off = 16; off > 0; off >>= 1)
        contrib += __shfl_down_sync(FULL, contrib, off);
    if (lane == 0) warpsum[wid] = contrib;
    __syncthreads();
    if (wid == 0) {
        float v = (lane < K2_THREADS / 32) ? warpsum[lane] : 0.f;
#pragma unroll
        for (int off = 2; off > 0; off >>= 1)
            v += __shfl_down_sync(FULL, v, off);
        if (lane == 0) atomicAdd(&g_cham, (double)v);
    }

    // last-block combine + state reset
    __threadfence();
    if (tid == 0) {
        unsigned t = atomicInc(&g_ctr, gridDim.x - 1);  // wraps to 0
        s_last = (t == gridDim.x - 1);
    }
    __syncthreads();
    if (s_last && tid == 0) {
        double diff     = g_acc[0] / (double)L_DIFF;
        double stylemse = g_acc[1] / (double)L_STYLE;
        double content  = g_acc[2] / (double)L_CONTENT;
        double identity = g_acc[3] / (double)L_ID;
        double cycle    = g_cham / (double)(BATCH * NPTS * 2);
        double style    = -stylemse;
        double tot = diff + 0.5 * style + 0.5 * content + cycle + 0.5 * identity;
        if (out_size > 0) out[0] = (float)diff;
        if (out_size > 1) out[1] = (float)style;
        if (out_size > 2) out[2] = (float)content;
        if (out_size > 3) out[3] = (float)cycle;
        if (out_size > 4) out[4] = (float)identity;
        if (out_size > 5) out[5] = (float)tot;
        for (int i = 6; i < out_size; i++) out[i] = 0.f;
        g_acc[0] = 0.0; g_acc[1] = 0.0; g_acc[2] = 0.0; g_acc[3] = 0.0;
        g_cham = 0.0;
    }
}

// ============================================================================
// Launch (graph-capturable). Inputs:
// 0 pred_noise, 1 target_noise, 2 style_sim, 3 style_real,
// 4 content_original, 5 content_generated, 6 x_cycle, 7 x_original, 8 x_identity
// ============================================================================
extern "C" void kernel_launch(void* const* d_in, const int* in_sizes, int n_in,
                              void* d_out, int out_size) {
    (void)n_in; (void)in_sizes;
    const float* pred  = (const float*)d_in[0];
    const float* targ  = (const float*)d_in[1];
    const float* ssim  = (const float*)d_in[2];
    const float* sreal = (const float*)d_in[3];
    const float* corg  = (const float*)d_in[4];
    const float* cgen  = (const float*)d_in[5];
    const float* xcyc  = (const float*)d_in[6];
    const float* xorg  = (const float*)d_in[7];
    const float* xid   = (const float*)d_in[8];
    float* out = (float*)d_out;

    build_mse_kernel<<<K1_BLOCKS, K1_THREADS>>>(xorg, xcyc, pred, targ,
                                                ssim, sreal, corg, cgen, xid);

    query_kernel<<<K2_BLOCKS, K2_THREADS>>>(out, out_size);
}

// round 12
// speedup vs baseline: 3.7631x; 3.7631x over previous
#include <cuda_runtime.h>
#include <cstdint>

// ============================================================================
// Problem shapes (fixed by reference setup_inputs)
// ============================================================================
#define BATCH      4
#define NPTS       8192
#define L_DIFF     98304       // 4*8192*3
#define L_STYLE    2048        // 4*512
#define L_CONTENT  1048576     // 4*1024*256
#define L_ID       98304

// Symmetric chamfer tiling: each block does a 1024-row x 512-col tile of the
// distance matrix ONCE, producing both row-mins (cd1) and col-mins (cd2).
// grid = CH_I*CH_J*BATCH = 8*16*4 = 512 chamfer blocks + 80 MSE = 592
//      = exactly 4 blocks per SM (148 SMs) -> one balanced wave.
#define THREADS     128
#define XT          8                      // rows per thread
#define XBLOCK      (THREADS * XT)         // 1024 rows per block
#define CH_I        (NPTS / XBLOCK)        // 8
#define JT          512                    // cols per block
#define CH_J        (NPTS / JT)            // 16
#define NPAIR       (JT / 2)               // 256 packed col-pairs
#define CH_BLOCKS   (CH_I * CH_J * BATCH)  // 512
#define MSE_BLOCKS  80
#define ALL_BLOCKS  (CH_BLOCKS + MSE_BLOCKS)

// ============================================================================
// Scratch (device globals; zero-initialized by CUDA).
// g_enc[i] = 0xFFFFFFFF - float_bits(min d2); d2 >= 0 so every encoded value
// > 0 ==> 0 is the atomicMax identity == static init == post-reset state.
// The LAST block of the fused kernel computes outputs and resets all state
// each call -> deterministic replays, no init launch, no final launch.
// ============================================================================
__device__ unsigned int g_enc[2 * BATCH * NPTS];   // [dir][b][i]
__device__ double       g_acc[4];                   // diff, style, content, identity
__device__ unsigned int g_ctr;                      // last-block ticket (auto-wrap)

// ============================================================================
// Packed f32x2 helpers (Blackwell; only reachable via PTX)
// ============================================================================
static __device__ __forceinline__ unsigned long long pk2(float lo, float hi) {
    unsigned long long r;
    asm("mov.b64 %0, {%1, %2};" : "=l"(r) : "f"(lo), "f"(hi));
    return r;
}
static __device__ __forceinline__ void upk2(unsigned long long v, float& lo, float& hi) {
    asm("mov.b64 {%0, %1}, %2;" : "=f"(lo), "=f"(hi) : "l"(v));
}
static __device__ __forceinline__ unsigned long long fma2(unsigned long long a,
                                                          unsigned long long b,
                                                          unsigned long long c) {
    unsigned long long d;
    asm("fma.rn.f32x2 %0, %1, %2, %3;" : "=l"(d) : "l"(a), "l"(b), "l"(c));
    return d;
}
static __device__ __forceinline__ unsigned long long mul2(unsigned long long a,
                                                          unsigned long long b) {
    unsigned long long d;
    asm("mul.rn.f32x2 %0, %1, %2;" : "=l"(d) : "l"(a), "l"(b));
    return d;
}
static __device__ __forceinline__ unsigned long long add2(unsigned long long a,
                                                          unsigned long long b) {
    unsigned long long d;
    asm("add.rn.f32x2 %0, %1, %2;" : "=l"(d) : "l"(a), "l"(b));
    return d;
}

// ============================================================================
// Symmetric chamfer tile (UNCHANGED from the 90.1us run).
// rows = x_original[b]  (row-min -> cd1 / g_enc dir0)
// cols = x_cycle[b]     (col-min -> cd2 / g_enc dir1)
// Per (row r, col-pair p): s = (-2x).y (mul2 + 2 fma2), then
//   t_row = s + q_j   -> row accumulator (registers)
//   t_col = s + rsq_i -> fold over r, butterfly over warp, stage in shared.
// d2_row = rsq_i + min_j t_row ; d2_col = q_j + min_i t_col.
// ============================================================================
static __device__ __forceinline__ void chamfer_tile(
    int bid, const float* __restrict__ xo, const float* __restrict__ xc,
    unsigned long long* s_ab, unsigned long long* s_cd,
    unsigned long long* s_col) {

    const int b  = bid >> 7;           // batch
    const int ic = (bid >> 4) & 7;     // i-chunk
    const int jc = bid & 15;           // j-chunk
    const float* X = xo + (size_t)b * NPTS * 3;
    const float* Y = xc + (size_t)b * NPTS * 3;
    unsigned int* enc_row = g_enc + (size_t)b * NPTS;            // dir0
    unsigned int* enc_col = g_enc + (size_t)(BATCH + b) * NPTS;  // dir1

    const int t    = threadIdx.x;
    const int lane = t & 31;
    const int wid  = t >> 5;
    const int row0 = ic * XBLOCK + t;

    unsigned long long nx[XT], ny[XT], nz[XT], rsq2[XT];
    float rmin[XT];
#pragma unroll
    for (int r = 0; r < XT; r++) {
        int i = row0 + r * THREADS;
        float a = X[3 * i], bb = X[3 * i + 1], c = X[3 * i + 2];
        nx[r] = pk2(-2.0f * a, -2.0f * a);
        ny[r] = pk2(-2.0f * bb, -2.0f * bb);
        nz[r] = pk2(-2.0f * c, -2.0f * c);
        float q = a * a + bb * bb + c * c;
        rsq2[r] = pk2(q, q);
        rmin[r] = 3.4e38f;
    }

    // y tile (512 cols as 256 pairs), interleaved for LDS.128:
    // s_ab[2p]={x,x'}, s_ab[2p+1]={y,y'}; s_cd[2p]={z,z'}, s_cd[2p+1]={q,q'}
    const int jbase = jc * JT;
    for (int p = t; p < NPAIR; p += THREADS) {
        const float* ya = Y + 3 * (jbase + 2 * p);
        float ax = ya[0], ay = ya[1], az = ya[2];
        float bx = ya[3], by = ya[4], bz = ya[5];
        s_ab[2 * p]     = pk2(ax, bx);
        s_ab[2 * p + 1] = pk2(ay, by);
        s_cd[2 * p]     = pk2(az, bz);
        s_cd[2 * p + 1] = pk2(ax * ax + ay * ay + az * az,
                              bx * bx + by * by + bz * bz);
    }
    __syncthreads();

    for (int p = 0; p < NPAIR; p++) {
        // warp-broadcast 128-bit loads: conflict-free
        ulonglong2 v1 = *(const ulonglong2*)(s_ab + 2 * p);  // yx, yy
        ulonglong2 v2 = *(const ulonglong2*)(s_cd + 2 * p);  // yz, yq
        float cL = 3.4e38f, cH = 3.4e38f;
#pragma unroll
        for (int r = 0; r < XT; r++) {
            unsigned long long s = mul2(nx[r], v1.x);
            s = fma2(ny[r], v1.y, s);
            s = fma2(nz[r], v2.x, s);
            unsigned long long tr = add2(s, v2.y);     // + q_j
            unsigned long long tc = add2(s, rsq2[r]);  // + rsq_i
            float rl, rh;  upk2(tr, rl, rh);
            rmin[r] = fminf(rmin[r], fminf(rl, rh));
            float c0, c1;  upk2(tc, c0, c1);
            cL = fminf(cL, c0);
            cH = fminf(cH, c1);
        }
        // warp butterfly: min over this warp's 256 rows for cols (2p, 2p+1)
#pragma unroll
        for (int off = 16; off > 0; off >>= 1) {
            cL = fminf(cL, __shfl_xor_sync(0xFFFFFFFFu, cL, off));
            cH = fminf(cH, __shfl_xor_sync(0xFFFFFFFFu, cH, off));
        }
        if (lane == 0) s_col[wid * NPAIR + p] = pk2(cL, cH);
    }

    // row epilogue
#pragma unroll
    for (int r = 0; r < XT; r++) {
        int i = row0 + r * THREADS;
        float q, dum;  upk2(rsq2[r], q, dum);
        float d2 = fmaxf(q + rmin[r], 0.0f);
        atomicMax(enc_row + i, 0xFFFFFFFFu - __float_as_uint(d2));
    }

    // col epilogue: merge 4 warps, add q_j, clamp, encode
    __syncthreads();
    for (int p = t; p < NPAIR; p += THREADS) {
        float aL, aH, bL, bH;
        upk2(s_col[0 * NPAIR + p], aL, aH);
        upk2(s_col[1 * NPAIR + p], bL, bH);
        aL = fminf(aL, bL);  aH = fminf(aH, bH);
        upk2(s_col[2 * NPAIR + p], bL, bH);
        aL = fminf(aL, bL);  aH = fminf(aH, bH);
        upk2(s_col[3 * NPAIR + p], bL, bH);
        aL = fminf(aL, bL);  aH = fminf(aH, bH);
        float q0, q1;  upk2(s_cd[2 * p + 1], q0, q1);
        float d2a = fmaxf(q0 + aL, 0.0f);
        float d2b = fmaxf(q1 + aH, 0.0f);
        int j = jbase + 2 * p;
        atomicMax(enc_col + j,     0xFFFFFFFFu - __float_as_uint(d2a));
        atomicMax(enc_col + j + 1, 0xFFFFFFFFu - __float_as_uint(d2b));
    }
}

// ============================================================================
// MSE part (80 blocks): all 4 sums, float4-vectorized -> g_acc.
// ============================================================================
static __device__ __forceinline__ float mse_part_v4(const float4* __restrict__ a,
                                                    const float4* __restrict__ b,
                                                    int n4, int gid, int stride) {
    float s = 0.f;
    for (int i = gid; i < n4; i += stride) {
        float4 va = a[i], vb = b[i];
        float d0 = va.x - vb.x, d1 = va.y - vb.y, d2 = va.z - vb.z, d3 = va.w - vb.w;
        s += d0 * d0 + d1 * d1 + d2 * d2 + d3 * d3;
    }
    return s;
}

static __device__ __forceinline__ void mse_blocks(
    int m, const float* pred, const float* targ, const float* ssim,
    const float* sreal, const float* corg, const float* cgen,
    const float* xorg, const float* xid, float* sm) {

    const int gid    = m * THREADS + threadIdx.x;
    const int stride = MSE_BLOCKS * THREADS;

    float s[4];
    s[0] = mse_part_v4((const float4*)pred, (const float4*)targ,  L_DIFF / 4,    gid, stride);
    s[1] = mse_part_v4((const float4*)ssim, (const float4*)sreal, L_STYLE / 4,   gid, stride);
    s[2] = mse_part_v4((const float4*)corg, (const float4*)cgen,  L_CONTENT / 4, gid, stride);
    s[3] = mse_part_v4((const float4*)xorg, (const float4*)xid,   L_ID / 4,      gid, stride);

    if (threadIdx.x < 4) sm[threadIdx.x] = 0.f;
    __syncthreads();
#pragma unroll
    for (int k = 0; k < 4; k++) {
#pragma unroll
        for (int off = 16; off > 0; off >>= 1)
            s[k] += __shfl_down_sync(0xFFFFFFFFu, s[k], off);
        if ((threadIdx.x & 31) == 0) atomicAdd(&sm[k], s[k]);
    }
    __syncthreads();
    if (threadIdx.x < 4) atomicAdd(&g_acc[threadIdx.x], (double)sm[threadIdx.x]);
}

// ============================================================================
// Fused kernel: blocks [0,512) symmetric chamfer tiles, [512,592) MSE,
// then the LAST block to finish (ticket) computes all outputs and resets
// state. Chamfer atomics are visible: every block threadfences before its
// ticket increment, and the last block reads g_enc only after winning it.
// ============================================================================
__global__ void __launch_bounds__(THREADS, 4)
fused_kernel(const float* __restrict__ xo,   const float* __restrict__ xc,
             const float* __restrict__ pred, const float* __restrict__ targ,
             const float* __restrict__ ssim, const float* __restrict__ sreal,
             const float* __restrict__ corg, const float* __restrict__ cgen,
             const float* __restrict__ xid,
             float* __restrict__ out, int out_size) {
    __shared__ __align__(16) unsigned long long s_ab[JT];
    __shared__ __align__(16) unsigned long long s_cd[JT];
    __shared__ __align__(16) unsigned long long s_col[4 * NPAIR];
    __shared__ float s_fin[THREADS / 32];
    __shared__ bool  s_last;

    const int bid = blockIdx.x;
    if (bid < CH_BLOCKS) {
        chamfer_tile(bid, xo, xc, s_ab, s_cd, s_col);
    } else {
        mse_blocks(bid - CH_BLOCKS, pred, targ, ssim, sreal, corg, cgen, xo, xid,
                   (float*)s_col);
    }

    // ---- last-block finalization ----
    __threadfence();
    if (threadIdx.x == 0) {
        unsigned t = atomicInc(&g_ctr, gridDim.x - 1);  // wraps to 0
        s_last = (t == gridDim.x - 1);
    }
    __syncthreads();
    if (!s_last) return;

    const int tid  = threadIdx.x;
    const int lane = tid & 31;
    const int wid  = tid >> 5;

    // sqrt-sum of all 65536 encoded mins + reset to 0 (atomicMax identity)
    float cham = 0.f;
    const int total = 2 * BATCH * NPTS;
    for (int i = tid; i < total; i += 4 * THREADS) {   // 4-way MLP
        unsigned u0 = g_enc[i];
        unsigned u1 = g_enc[i + THREADS];
        unsigned u2 = g_enc[i + 2 * THREADS];
        unsigned u3 = g_enc[i + 3 * THREADS];
        g_enc[i] = 0u; g_enc[i + THREADS] = 0u;
        g_enc[i + 2 * THREADS] = 0u; g_enc[i + 3 * THREADS] = 0u;
        cham += sqrtf(__uint_as_float(0xFFFFFFFFu - u0));
        cham += sqrtf(__uint_as_float(0xFFFFFFFFu - u1));
        cham += sqrtf(__uint_as_float(0xFFFFFFFFu - u2));
        cham += sqrtf(__uint_as_float(0xFFFFFFFFu - u3));
    }
#pragma unroll
    for (int off = 16; off > 0; off >>= 1)
        cham += __shfl_down_sync(0xFFFFFFFFu, cham, off);
    if (lane == 0) s_fin[wid] = cham;
    __syncthreads();

    if (tid == 0) {
        double chsum = 0.0;
#pragma unroll
        for (int w = 0; w < THREADS / 32; w++) chsum += (double)s_fin[w];
        double diff     = g_acc[0] / (double)L_DIFF;
        double stylemse = g_acc[1] / (double)L_STYLE;
        double content  = g_acc[2] / (double)L_CONTENT;
        double identity = g_acc[3] / (double)L_ID;
        double cycle    = chsum / (double)(BATCH * NPTS * 2);
        double style    = -stylemse;
        double tot = diff + 0.5 * style + 0.5 * content + cycle + 0.5 * identity;
        if (out_size > 0) out[0] = (float)diff;
        if (out_size > 1) out[1] = (float)style;
        if (out_size > 2) out[2] = (float)content;
        if (out_size > 3) out[3] = (float)cycle;
        if (out_size > 4) out[4] = (float)identity;
        if (out_size > 5) out[5] = (float)tot;
        for (int i = 6; i < out_size; i++) out[i] = 0.f;
        // clean accumulators for the next call
        g_acc[0] = 0.0; g_acc[1] = 0.0; g_acc[2] = 0.0; g_acc[3] = 0.0;
    }
}

// ============================================================================
// Launch (graph-capturable, ONE kernel). Inputs:
// 0 pred_noise, 1 target_noise, 2 style_sim, 3 style_real,
// 4 content_original, 5 content_generated, 6 x_cycle, 7 x_original, 8 x_identity
// ============================================================================
extern "C" void kernel_launch(void* const* d_in, const int* in_sizes, int n_in,
                              void* d_out, int out_size) {
    (void)n_in; (void)in_sizes;
    const float* pred  = (const float*)d_in[0];
    const float* targ  = (const float*)d_in[1];
    const float* ssim  = (const float*)d_in[2];
    const float* sreal = (const float*)d_in[3];
    const float* corg  = (const float*)d_in[4];
    const float* cgen  = (const float*)d_in[5];
    const float* xcyc  = (const float*)d_in[6];
    const float* xorg  = (const float*)d_in[7];
    const float* xid   = (const float*)d_in[8];
    float* out = (float*)d_out;

    fused_kernel<<<ALL_BLOCKS, THREADS>>>(xorg, xcyc, pred, targ, ssim, sreal,
                                          corg, cgen, xid, out, out_size);
}

// round 14
// speedup vs baseline: 4.8695x; 1.2940x over previous
#include <cuda_runtime.h>
#include <cstdint>

// ============================================================================
// Problem shapes (fixed by reference setup_inputs)
// ============================================================================
#define BATCH      4
#define NPTS       8192
#define L_DIFF     98304       // 4*8192*3
#define L_STYLE    2048        // 4*512
#define L_CONTENT  1048576     // 4*1024*256
#define L_ID       98304

// Symmetric chamfer tiling: each block does a 512-row x 512-col tile of the
// distance matrix ONCE, producing both row-mins (cd1) and col-mins (cd2).
// XT=4 keeps regs <= 64 so __launch_bounds__(128,8) gives 32 warps/SM
// (vs 16 at XT=8/96regs -> measured occ 19.8%, issue 53.5%: latency-bound).
// grid = CH_I*CH_J*BATCH = 16*16*4 = 1024 chamfer blocks + 80 MSE = 1104
//      ~= 7.5 blocks/SM -> single balanced wave at 8 resident blocks.
#define THREADS     128
#define XT          4                      // rows per thread
#define XBLOCK      (THREADS * XT)         // 512 rows per block
#define CH_I        (NPTS / XBLOCK)        // 16
#define JT          512                    // cols per block
#define CH_J        (NPTS / JT)            // 16
#define NPAIR       (JT / 2)               // 256 packed col-pairs
#define CH_BLOCKS   (CH_I * CH_J * BATCH)  // 1024
#define MSE_BLOCKS  80
#define ALL_BLOCKS  (CH_BLOCKS + MSE_BLOCKS)

// final kernel: 256 blocks x 256 threads = 65536 threads = one element each
#define FIN_BLOCKS  256
#define FIN_THREADS 256

// ============================================================================
// Scratch (device globals; zero-initialized by CUDA).
// g_enc[i] = 0xFFFFFFFF - float_bits(min d2); d2 >= 0 so every encoded value
// > 0 ==> 0 is the atomicMax identity == static init == post-reset state.
// final_kernel resets all state each call -> deterministic, no init launch.
// ============================================================================
__device__ unsigned int g_enc[2 * BATCH * NPTS];   // [dir][b][i]
__device__ double       g_acc[4];                   // diff, style, content, identity
__device__ double       g_cham;                     // sum of sqrt(min d2)
__device__ unsigned int g_ctr;                      // last-block ticket (auto-wrap)

// ============================================================================
// Packed f32x2 helpers (Blackwell; only reachable via PTX)
// ============================================================================
static __device__ __forceinline__ unsigned long long pk2(float lo, float hi) {
    unsigned long long r;
    asm("mov.b64 %0, {%1, %2};" : "=l"(r) : "f"(lo), "f"(hi));
    return r;
}
static __device__ __forceinline__ void upk2(unsigned long long v, float& lo, float& hi) {
    asm("mov.b64 {%0, %1}, %2;" : "=f"(lo), "=f"(hi) : "l"(v));
}
static __device__ __forceinline__ unsigned long long fma2(unsigned long long a,
                                                          unsigned long long b,
                                                          unsigned long long c) {
    unsigned long long d;
    asm("fma.rn.f32x2 %0, %1, %2, %3;" : "=l"(d) : "l"(a), "l"(b), "l"(c));
    return d;
}
static __device__ __forceinline__ unsigned long long mul2(unsigned long long a,
                                                          unsigned long long b) {
    unsigned long long d;
    asm("mul.rn.f32x2 %0, %1, %2;" : "=l"(d) : "l"(a), "l"(b));
    return d;
}
static __device__ __forceinline__ unsigned long long add2(unsigned long long a,
                                                          unsigned long long b) {
    unsigned long long d;
    asm("add.rn.f32x2 %0, %1, %2;" : "=l"(d) : "l"(a), "l"(b));
    return d;
}

// ============================================================================
// Symmetric chamfer tile (hot loop identical in form to the 90.1us run,
// only XT=4 and the block decomposition changed).
// rows = x_original[b]  (row-min -> cd1 / g_enc dir0)
// cols = x_cycle[b]     (col-min -> cd2 / g_enc dir1)
// ============================================================================
static __device__ __forceinline__ void chamfer_tile(
    int bid, const float* __restrict__ xo, const float* __restrict__ xc,
    unsigned long long* s_ab, unsigned long long* s_cd,
    unsigned long long* s_col) {

    const int b  = bid >> 8;           // batch (0..3)
    const int ic = (bid >> 4) & 15;    // i-chunk (0..15)
    const int jc = bid & 15;           // j-chunk (0..15)
    const float* X = xo + (size_t)b * NPTS * 3;
    const float* Y = xc + (size_t)b * NPTS * 3;
    unsigned int* enc_row = g_enc + (size_t)b * NPTS;            // dir0
    unsigned int* enc_col = g_enc + (size_t)(BATCH + b) * NPTS;  // dir1

    const int t    = threadIdx.x;
    const int lane = t & 31;
    const int wid  = t >> 5;
    const int row0 = ic * XBLOCK + t;

    unsigned long long nx[XT], ny[XT], nz[XT], rsq2[XT];
    float rmin[XT];
#pragma unroll
    for (int r = 0; r < XT; r++) {
        int i = row0 + r * THREADS;
        float a = X[3 * i], bb = X[3 * i + 1], c = X[3 * i + 2];
        nx[r] = pk2(-2.0f * a, -2.0f * a);
        ny[r] = pk2(-2.0f * bb, -2.0f * bb);
        nz[r] = pk2(-2.0f * c, -2.0f * c);
        float q = a * a + bb * bb + c * c;
        rsq2[r] = pk2(q, q);
        rmin[r] = 3.4e38f;
    }

    // y tile (512 cols as 256 pairs), interleaved for LDS.128:
    // s_ab[2p]={x,x'}, s_ab[2p+1]={y,y'}; s_cd[2p]={z,z'}, s_cd[2p+1]={q,q'}
    const int jbase = jc * JT;
    for (int p = t; p < NPAIR; p += THREADS) {
        const float* ya = Y + 3 * (jbase + 2 * p);
        float ax = ya[0], ay = ya[1], az = ya[2];
        float bx = ya[3], by = ya[4], bz = ya[5];
        s_ab[2 * p]     = pk2(ax, bx);
        s_ab[2 * p + 1] = pk2(ay, by);
        s_cd[2 * p]     = pk2(az, bz);
        s_cd[2 * p + 1] = pk2(ax * ax + ay * ay + az * az,
                              bx * bx + by * by + bz * bz);
    }
    __syncthreads();

    for (int p = 0; p < NPAIR; p++) {
        // warp-broadcast 128-bit loads: conflict-free
        ulonglong2 v1 = *(const ulonglong2*)(s_ab + 2 * p);  // yx, yy
        ulonglong2 v2 = *(const ulonglong2*)(s_cd + 2 * p);  // yz, yq
        float cL = 3.4e38f, cH = 3.4e38f;
#pragma unroll
        for (int r = 0; r < XT; r++) {
            unsigned long long s = mul2(nx[r], v1.x);
            s = fma2(ny[r], v1.y, s);
            s = fma2(nz[r], v2.x, s);
            unsigned long long tr = add2(s, v2.y);     // + q_j
            unsigned long long tc = add2(s, rsq2[r]);  // + rsq_i
            float rl, rh;  upk2(tr, rl, rh);
            rmin[r] = fminf(rmin[r], fminf(rl, rh));
            float c0, c1;  upk2(tc, c0, c1);
            cL = fminf(cL, c0);
            cH = fminf(cH, c1);
        }
        // warp butterfly: min over this warp's 128 rows for cols (2p, 2p+1)
#pragma unroll
        for (int off = 16; off > 0; off >>= 1) {
            cL = fminf(cL, __shfl_xor_sync(0xFFFFFFFFu, cL, off));
            cH = fminf(cH, __shfl_xor_sync(0xFFFFFFFFu, cH, off));
        }
        if (lane == 0) s_col[wid * NPAIR + p] = pk2(cL, cH);
    }

    // row epilogue
#pragma unroll
    for (int r = 0; r < XT; r++) {
        int i = row0 + r * THREADS;
        float q, dum;  upk2(rsq2[r], q, dum);
        float d2 = fmaxf(q + rmin[r], 0.0f);
        atomicMax(enc_row + i, 0xFFFFFFFFu - __float_as_uint(d2));
    }

    // col epilogue: merge 4 warps, add q_j, clamp, encode
    __syncthreads();
    for (int p = t; p < NPAIR; p += THREADS) {
        float aL, aH, bL, bH;
        upk2(s_col[0 * NPAIR + p], aL, aH);
        upk2(s_col[1 * NPAIR + p], bL, bH);
        aL = fminf(aL, bL);  aH = fminf(aH, bH);
        upk2(s_col[2 * NPAIR + p], bL, bH);
        aL = fminf(aL, bL);  aH = fminf(aH, bH);
        upk2(s_col[3 * NPAIR + p], bL, bH);
        aL = fminf(aL, bL);  aH = fminf(aH, bH);
        float q0, q1;  upk2(s_cd[2 * p + 1], q0, q1);
        float d2a = fmaxf(q0 + aL, 0.0f);
        float d2b = fmaxf(q1 + aH, 0.0f);
        int j = jbase + 2 * p;
        atomicMax(enc_col + j,     0xFFFFFFFFu - __float_as_uint(d2a));
        atomicMax(enc_col + j + 1, 0xFFFFFFFFu - __float_as_uint(d2b));
    }
}

// ============================================================================
// MSE part (80 blocks): all 4 sums, float4-vectorized -> g_acc.
// ============================================================================
static __device__ __forceinline__ float mse_part_v4(const float4* __restrict__ a,
                                                    const float4* __restrict__ b,
                                                    int n4, int gid, int stride) {
    float s = 0.f;
    for (int i = gid; i < n4; i += stride) {
        float4 va = a[i], vb = b[i];
        float d0 = va.x - vb.x, d1 = va.y - vb.y, d2 = va.z - vb.z, d3 = va.w - vb.w;
        s += d0 * d0 + d1 * d1 + d2 * d2 + d3 * d3;
    }
    return s;
}

static __device__ __forceinline__ void mse_blocks(
    int m, const float* pred, const float* targ, const float* ssim,
    const float* sreal, const float* corg, const float* cgen,
    const float* xorg, const float* xid, float* sm) {

    const int gid    = m * THREADS + threadIdx.x;
    const int stride = MSE_BLOCKS * THREADS;

    float s[4];
    s[0] = mse_part_v4((const float4*)pred, (const float4*)targ,  L_DIFF / 4,    gid, stride);
    s[1] = mse_part_v4((const float4*)ssim, (const float4*)sreal, L_STYLE / 4,   gid, stride);
    s[2] = mse_part_v4((const float4*)corg, (const float4*)cgen,  L_CONTENT / 4, gid, stride);
    s[3] = mse_part_v4((const float4*)xorg, (const float4*)xid,   L_ID / 4,      gid, stride);

    if (threadIdx.x < 4) sm[threadIdx.x] = 0.f;
    __syncthreads();
#pragma unroll
    for (int k = 0; k < 4; k++) {
#pragma unroll
        for (int off = 16; off > 0; off >>= 1)
            s[k] += __shfl_down_sync(0xFFFFFFFFu, s[k], off);
        if ((threadIdx.x & 31) == 0) atomicAdd(&sm[k], s[k]);
    }
    __syncthreads();
    if (threadIdx.x < 4) atomicAdd(&g_acc[threadIdx.x], (double)sm[threadIdx.x]);
}

// ============================================================================
// Fused kernel: blocks [0,1024) symmetric chamfer tiles, [1024,1104) MSE.
// launch_bounds(128, 8): forces regs <= 64 -> 8 blocks/SM = 32 warps (50% occ).
// ============================================================================
__global__ void __launch_bounds__(THREADS, 8)
fused_kernel(const float* __restrict__ xo,   const float* __restrict__ xc,
             const float* __restrict__ pred, const float* __restrict__ targ,
             const float* __restrict__ ssim, const float* __restrict__ sreal,
             const float* __restrict__ corg, const float* __restrict__ cgen,
             const float* __restrict__ xid) {
    __shared__ __align__(16) unsigned long long s_ab[JT];
    __shared__ __align__(16) unsigned long long s_cd[JT];
    __shared__ __align__(16) unsigned long long s_col[4 * NPAIR];

    const int bid = blockIdx.x;
    if (bid < CH_BLOCKS) {
        chamfer_tile(bid, xo, xc, s_ab, s_cd, s_col);
    } else {
        mse_blocks(bid - CH_BLOCKS, pred, targ, ssim, sreal, corg, cgen, xo, xid,
                   (float*)s_col);
    }
}

// ============================================================================
// Final kernel: 65536 threads, one encoded min each: sqrt-sum + reset,
// last block combines and writes the 6 outputs, cleans state.
// ============================================================================
__global__ void __launch_bounds__(FIN_THREADS)
final_kernel(float* __restrict__ out, int out_size) {
    __shared__ float warpsum[FIN_THREADS / 32];
    __shared__ bool  s_last;
    const int tid  = threadIdx.x;
    const int lane = tid & 31;
    const int wid  = tid >> 5;
    const int gid  = blockIdx.x * FIN_THREADS + tid;

    unsigned u = g_enc[gid];
    g_enc[gid] = 0u;                        // clean (atomicMax identity)
    float cham = sqrtf(__uint_as_float(0xFFFFFFFFu - u));

#pragma unroll
    for (int off = 16; off > 0; off >>= 1)
        cham += __shfl_down_sync(0xFFFFFFFFu, cham, off);
    if (lane == 0) warpsum[wid] = cham;
    __syncthreads();
    if (wid == 0) {
        float v = (lane < FIN_THREADS / 32) ? warpsum[lane] : 0.f;
#pragma unroll
        for (int off = 4; off > 0; off >>= 1)
            v += __shfl_down_sync(0xFFFFFFFFu, v, off);
        if (lane == 0) atomicAdd(&g_cham, (double)v);
    }

    __threadfence();
    if (tid == 0) {
        unsigned t = atomicInc(&g_ctr, gridDim.x - 1);  // wraps to 0
        s_last = (t == gridDim.x - 1);
    }
    __syncthreads();
    if (s_last && tid == 0) {
        double diff     = g_acc[0] / (double)L_DIFF;
        double stylemse = g_acc[1] / (double)L_STYLE;
        double content  = g_acc[2] / (double)L_CONTENT;
        double identity = g_acc[3] / (double)L_ID;
        double cycle    = g_cham / (double)(BATCH * NPTS * 2);
        double style    = -stylemse;
        double tot = diff + 0.5 * style + 0.5 * content + cycle + 0.5 * identity;
        if (out_size > 0) out[0] = (float)diff;
        if (out_size > 1) out[1] = (float)style;
        if (out_size > 2) out[2] = (float)content;
        if (out_size > 3) out[3] = (float)cycle;
        if (out_size > 4) out[4] = (float)identity;
        if (out_size > 5) out[5] = (float)tot;
        for (int i = 6; i < out_size; i++) out[i] = 0.f;
        g_acc[0] = 0.0; g_acc[1] = 0.0; g_acc[2] = 0.0; g_acc[3] = 0.0;
        g_cham = 0.0;
    }
}

// ============================================================================
// Launch (graph-capturable). Inputs:
// 0 pred_noise, 1 target_noise, 2 style_sim, 3 style_real,
// 4 content_original, 5 content_generated, 6 x_cycle, 7 x_original, 8 x_identity
// ============================================================================
extern "C" void kernel_launch(void* const* d_in, const int* in_sizes, int n_in,
                              void* d_out, int out_size) {
    (void)n_in; (void)in_sizes;
    const float* pred  = (const float*)d_in[0];
    const float* targ  = (const float*)d_in[1];
    const float* ssim  = (const float*)d_in[2];
    const float* sreal = (const float*)d_in[3];
    const float* corg  = (const float*)d_in[4];
    const float* cgen  = (const float*)d_in[5];
    const float* xcyc  = (const float*)d_in[6];
    const float* xorg  = (const float*)d_in[7];
    const float* xid   = (const float*)d_in[8];
    float* out = (float*)d_out;

    fused_kernel<<<ALL_BLOCKS, THREADS>>>(xorg, xcyc, pred, targ, ssim, sreal,
                                          corg, cgen, xid);

    final_kernel<<<FIN_BLOCKS, FIN_THREADS>>>(out, out_size);
}

// round 15
// speedup vs baseline: 5.7731x; 1.1855x over previous
#include <cuda_runtime.h>
#include <cstdint>

// ============================================================================
// Problem shapes (fixed by reference setup_inputs)
// ============================================================================
#define BATCH      4
#define NPTS       8192
#define L_DIFF     98304       // 4*8192*3
#define L_STYLE    2048        // 4*512
#define L_CONTENT  1048576     // 4*1024*256
#define L_ID       98304

// Symmetric chamfer, ROW-PAIR PACKED: each packed f32x2 register holds TWO
// DIFFERENT x-rows; y columns are stored DUPLICATED in shared. Same 8 rows
// per thread as the 90.1us best, but x-register footprint halved -> 24
// warps/SM via __launch_bounds__(128,6) with unchanged ops/pair.
// Block tile: 1024 rows x 256 cols. grid = 8*32*4 = 1024 chamfer + 80 MSE.
#define THREADS     128
#define RP          4                      // row-pairs per thread (8 rows)
#define XBLOCK      (THREADS * 2 * RP)     // 1024 rows per block
#define CH_I        (NPTS / XBLOCK)        // 8
#define JT          256                    // cols per block
#define CH_J        (NPTS / JT)            // 32
#define NPAIR       (JT / 2)               // 128 col-pairs
#define CH_BLOCKS   (CH_I * CH_J * BATCH)  // 1024
#define MSE_BLOCKS  80
#define ALL_BLOCKS  (CH_BLOCKS + MSE_BLOCKS)

// final kernel (best measured config: 128 blocks -> 7.9us)
#define FIN_BLOCKS  128
#define FIN_THREADS 256

// ============================================================================
// Scratch (device globals; zero-initialized by CUDA).
// g_enc[i] = 0xFFFFFFFF - float_bits(min d2); d2 >= 0 so every encoded value
// > 0 ==> 0 is the atomicMax identity == static init == post-reset state.
// final_kernel resets all state each call -> deterministic, no init launch.
// ============================================================================
__device__ unsigned int g_enc[2 * BATCH * NPTS];   // [dir][b][i]
__device__ double       g_acc[4];                   // diff, style, content, identity
__device__ double       g_cham;                     // sum of sqrt(min d2)
__device__ unsigned int g_ctr;                      // last-block ticket (auto-wrap)

// ============================================================================
// Packed f32x2 helpers (Blackwell; only reachable via PTX)
// ============================================================================
static __device__ __forceinline__ unsigned long long pk2(float lo, float hi) {
    unsigned long long r;
    asm("mov.b64 %0, {%1, %2};" : "=l"(r) : "f"(lo), "f"(hi));
    return r;
}
static __device__ __forceinline__ void upk2(unsigned long long v, float& lo, float& hi) {
    asm("mov.b64 {%0, %1}, %2;" : "=f"(lo), "=f"(hi) : "l"(v));
}
static __device__ __forceinline__ unsigned long long fma2(unsigned long long a,
                                                          unsigned long long b,
                                                          unsigned long long c) {
    unsigned long long d;
    asm("fma.rn.f32x2 %0, %1, %2, %3;" : "=l"(d) : "l"(a), "l"(b), "l"(c));
    return d;
}
static __device__ __forceinline__ unsigned long long mul2(unsigned long long a,
                                                          unsigned long long b) {
    unsigned long long d;
    asm("mul.rn.f32x2 %0, %1, %2;" : "=l"(d) : "l"(a), "l"(b));
    return d;
}
static __device__ __forceinline__ unsigned long long add2(unsigned long long a,
                                                          unsigned long long b) {
    unsigned long long d;
    asm("add.rn.f32x2 %0, %1, %2;" : "=l"(d) : "l"(a), "l"(b));
    return d;
}

// ============================================================================
// Symmetric chamfer tile, row-pair packed.
// rows = x_original[b]  (row-min -> cd1 / g_enc dir0)
// cols = x_cycle[b]     (col-min -> cd2 / g_enc dir1)
// Per (row-pair rp, col j): s = (-2x_pair).y_dup (mul2+2*fma2), then
//   tr = s + (q_j,q_j)      -> row-min accumulators (two scalars per rp)
//   tc = s + (rsqA,rsqB)    -> fold over rp+halves, butterfly, stage shared.
// ============================================================================
static __device__ __forceinline__ void chamfer_tile(
    int bid, const float* __restrict__ xo, const float* __restrict__ xc,
    unsigned long long* s_y, unsigned long long* s_colp) {

    const int b  = bid >> 8;           // batch (0..3)
    const int ic = (bid >> 5) & 7;     // i-chunk (0..7)
    const int jc = bid & 31;           // j-chunk (0..31)
    const float* X = xo + (size_t)b * NPTS * 3;
    const float* Y = xc + (size_t)b * NPTS * 3;
    unsigned int* enc_row = g_enc + (size_t)b * NPTS;            // dir0
    unsigned int* enc_col = g_enc + (size_t)(BATCH + b) * NPTS;  // dir1

    const int t    = threadIdx.x;
    const int lane = t & 31;
    const int wid  = t >> 5;
    const int row0 = ic * XBLOCK + t;

    // packed (-2x) per row-PAIR: lo = row row0+2rp*T, hi = row row0+(2rp+1)*T
    unsigned long long npx[RP], npy[RP], npz[RP], rsqp[RP];
    float rminA[RP], rminB[RP];
#pragma unroll
    for (int rp = 0; rp < RP; rp++) {
        int iA = row0 + (2 * rp) * THREADS;
        int iB = row0 + (2 * rp + 1) * THREADS;
        float ax = X[3 * iA], ay = X[3 * iA + 1], az = X[3 * iA + 2];
        float bx = X[3 * iB], by = X[3 * iB + 1], bz = X[3 * iB + 2];
        npx[rp]  = pk2(-2.0f * ax, -2.0f * bx);
        npy[rp]  = pk2(-2.0f * ay, -2.0f * by);
        npz[rp]  = pk2(-2.0f * az, -2.0f * bz);
        rsqp[rp] = pk2(ax * ax + ay * ay + az * az,
                       bx * bx + by * by + bz * bz);
        rminA[rp] = 3.4e38f;
        rminB[rp] = 3.4e38f;
    }

    // y tile: per col j, 4 DUPLICATED u64: (x,x),(y,y),(z,z),(q,q) at s_y[4j..]
    const int jbase = jc * JT;
    for (int j = t; j < JT; j += THREADS) {
        const float* yj = Y + 3 * (jbase + j);
        float yx = yj[0], yy = yj[1], yz = yj[2];
        s_y[4 * j]     = pk2(yx, yx);
        s_y[4 * j + 1] = pk2(yy, yy);
        s_y[4 * j + 2] = pk2(yz, yz);
        float q = yx * yx + yy * yy + yz * yz;
        s_y[4 * j + 3] = pk2(q, q);
    }
    __syncthreads();

#pragma unroll 2
    for (int cp = 0; cp < NPAIR; cp++) {
        // two cols j0=2cp, j1=2cp+1; 4 broadcast LDS.128
        ulonglong2 va = *(const ulonglong2*)(s_y + 8 * cp);      // x0d, y0d
        ulonglong2 vb = *(const ulonglong2*)(s_y + 8 * cp + 2);  // z0d, q0d
        ulonglong2 vc = *(const ulonglong2*)(s_y + 8 * cp + 4);  // x1d, y1d
        ulonglong2 vd = *(const ulonglong2*)(s_y + 8 * cp + 6);  // z1d, q1d
        float cmin0 = 3.4e38f, cmin1 = 3.4e38f;
#pragma unroll
        for (int rp = 0; rp < RP; rp++) {
            // col j0
            unsigned long long s0 = mul2(npx[rp], va.x);
            s0 = fma2(npy[rp], va.y, s0);
            s0 = fma2(npz[rp], vb.x, s0);
            unsigned long long tr0 = add2(s0, vb.y);      // + q_j0 (dup)
            unsigned long long tc0 = add2(s0, rsqp[rp]);  // + (rsqA, rsqB)
            // col j1
            unsigned long long s1 = mul2(npx[rp], vc.x);
            s1 = fma2(npy[rp], vc.y, s1);
            s1 = fma2(npz[rp], vd.x, s1);
            unsigned long long tr1 = add2(s1, vd.y);
            unsigned long long tc1 = add2(s1, rsqp[rp]);

            float lA, lB;
            upk2(tr0, lA, lB);
            rminA[rp] = fminf(rminA[rp], lA);
            rminB[rp] = fminf(rminB[rp], lB);
            upk2(tr1, lA, lB);
            rminA[rp] = fminf(rminA[rp], lA);
            rminB[rp] = fminf(rminB[rp], lB);

            upk2(tc0, lA, lB);
            cmin0 = fminf(cmin0, fminf(lA, lB));
            upk2(tc1, lA, lB);
            cmin1 = fminf(cmin1, fminf(lA, lB));
        }
        // warp butterfly: min over this warp's 256 rows for cols (j0, j1)
#pragma unroll
        for (int off = 16; off > 0; off >>= 1) {
            cmin0 = fminf(cmin0, __shfl_xor_sync(0xFFFFFFFFu, cmin0, off));
            cmin1 = fminf(cmin1, __shfl_xor_sync(0xFFFFFFFFu, cmin1, off));
        }
        if (lane == 0) s_colp[wid * NPAIR + cp] = pk2(cmin0, cmin1);
    }

    // row epilogue
#pragma unroll
    for (int rp = 0; rp < RP; rp++) {
        float qA, qB;
        upk2(rsqp[rp], qA, qB);
        int iA = row0 + (2 * rp) * THREADS;
        int iB = row0 + (2 * rp + 1) * THREADS;
        float d2A = fmaxf(qA + rminA[rp], 0.0f);
        float d2B = fmaxf(qB + rminB[rp], 0.0f);
        atomicMax(enc_row + iA, 0xFFFFFFFFu - __float_as_uint(d2A));
        atomicMax(enc_row + iB, 0xFFFFFFFFu - __float_as_uint(d2B));
    }

    // col epilogue: merge 4 warps per col-pair, add q_j, clamp, encode
    __syncthreads();
    for (int cp = t; cp < NPAIR; cp += THREADS) {
        float m0, m1, b0, b1;
        upk2(s_colp[0 * NPAIR + cp], m0, m1);
        upk2(s_colp[1 * NPAIR + cp], b0, b1);
        m0 = fminf(m0, b0);  m1 = fminf(m1, b1);
        upk2(s_colp[2 * NPAIR + cp], b0, b1);
        m0 = fminf(m0, b0);  m1 = fminf(m1, b1);
        upk2(s_colp[3 * NPAIR + cp], b0, b1);
        m0 = fminf(m0, b0);  m1 = fminf(m1, b1);
        float q0, du, q1;
        upk2(s_y[8 * cp + 3], q0, du);
        upk2(s_y[8 * cp + 7], q1, du);
        float d20 = fmaxf(q0 + m0, 0.0f);
        float d21 = fmaxf(q1 + m1, 0.0f);
        int j = jbase + 2 * cp;
        atomicMax(enc_col + j,     0xFFFFFFFFu - __float_as_uint(d20));
        atomicMax(enc_col + j + 1, 0xFFFFFFFFu - __float_as_uint(d21));
    }
}

// ============================================================================
// MSE part (80 blocks): all 4 sums, float4-vectorized -> g_acc.
// ============================================================================
static __device__ __forceinline__ float mse_part_v4(const float4* __restrict__ a,
                                                    const float4* __restrict__ b,
                                                    int n4, int gid, int stride) {
    float s = 0.f;
    for (int i = gid; i < n4; i += stride) {
        float4 va = a[i], vb = b[i];
        float d0 = va.x - vb.x, d1 = va.y - vb.y, d2 = va.z - vb.z, d3 = va.w - vb.w;
        s += d0 * d0 + d1 * d1 + d2 * d2 + d3 * d3;
    }
    return s;
}

static __device__ __forceinline__ void mse_blocks(
    int m, const float* pred, const float* targ, const float* ssim,
    const float* sreal, const float* corg, const float* cgen,
    const float* xorg, const float* xid, float* sm) {

    const int gid    = m * THREADS + threadIdx.x;
    const int stride = MSE_BLOCKS * THREADS;

    float s[4];
    s[0] = mse_part_v4((const float4*)pred, (const float4*)targ,  L_DIFF / 4,    gid, stride);
    s[1] = mse_part_v4((const float4*)ssim, (const float4*)sreal, L_STYLE / 4,   gid, stride);
    s[2] = mse_part_v4((const float4*)corg, (const float4*)cgen,  L_CONTENT / 4, gid, stride);
    s[3] = mse_part_v4((const float4*)xorg, (const float4*)xid,   L_ID / 4,      gid, stride);

    if (threadIdx.x < 4) sm[threadIdx.x] = 0.f;
    __syncthreads();
#pragma unroll
    for (int k = 0; k < 4; k++) {
#pragma unroll
        for (int off = 16; off > 0; off >>= 1)
            s[k] += __shfl_down_sync(0xFFFFFFFFu, s[k], off);
        if ((threadIdx.x & 31) == 0) atomicAdd(&sm[k], s[k]);
    }
    __syncthreads();
    if (threadIdx.x < 4) atomicAdd(&g_acc[threadIdx.x], (double)sm[threadIdx.x]);
}

// ============================================================================
// Fused kernel: blocks [0,1024) chamfer tiles, [1024,1104) MSE.
// launch_bounds(128,6): regs <= 85 (no spill risk at ~60-70), 24 warps/SM.
// ============================================================================
__global__ void __launch_bounds__(THREADS, 6)
fused_kernel(const float* __restrict__ xo,   const float* __restrict__ xc,
             const float* __restrict__ pred, const float* __restrict__ targ,
             const float* __restrict__ ssim, const float* __restrict__ sreal,
             const float* __restrict__ corg, const float* __restrict__ cgen,
             const float* __restrict__ xid) {
    __shared__ __align__(16) unsigned long long s_y[4 * JT];        // 8 KB
    __shared__ __align__(16) unsigned long long s_colp[4 * NPAIR];  // 4 KB

    const int bid = blockIdx.x;
    if (bid < CH_BLOCKS) {
        chamfer_tile(bid, xo, xc, s_y, s_colp);
    } else {
        mse_blocks(bid - CH_BLOCKS, pred, targ, ssim, sreal, corg, cgen, xo, xid,
                   (float*)s_colp);
    }
}

// ============================================================================
// Final kernel: sqrt-sum of g_enc + reset, last block combines + writes out
// and cleans state. (128-block config: best measured, 7.9us.)
// ============================================================================
__global__ void __launch_bounds__(FIN_THREADS)
final_kernel(float* __restrict__ out, int out_size) {
    __shared__ float warpsum[FIN_THREADS / 32];
    __shared__ bool  s_last;
    const int tid  = threadIdx.x;
    const int lane = tid & 31;
    const int wid  = tid >> 5;
    const int gid  = blockIdx.x * FIN_THREADS + tid;
    const int stride = FIN_BLOCKS * FIN_THREADS;

    float cham = 0.f;
    const int total = 2 * BATCH * NPTS;
    for (int i = gid; i < total; i += stride) {
        unsigned u = g_enc[i];
        g_enc[i] = 0u;                      // clean (atomicMax identity)
        cham += sqrtf(__uint_as_float(0xFFFFFFFFu - u));
    }

#pragma unroll
    for (int off = 16; off > 0; off >>= 1)
        cham += __shfl_down_sync(0xFFFFFFFFu, cham, off);
    if (lane == 0) warpsum[wid] = cham;
    __syncthreads();
    if (wid == 0) {
        float v = (lane < FIN_THREADS / 32) ? warpsum[lane] : 0.f;
#pragma unroll
        for (int off = 4; off > 0; off >>= 1)
            v += __shfl_down_sync(0xFFFFFFFFu, v, off);
        if (lane == 0) atomicAdd(&g_cham, (double)v);
    }

    __threadfence();
    if (tid == 0) {
        unsigned t = atomicInc(&g_ctr, gridDim.x - 1);  // wraps to 0
        s_last = (t == gridDim.x - 1);
    }
    __syncthreads();
    if (s_last && tid == 0) {
        double diff     = g_acc[0] / (double)L_DIFF;
        double stylemse = g_acc[1] / (double)L_STYLE;
        double content  = g_acc[2] / (double)L_CONTENT;
        double identity = g_acc[3] / (double)L_ID;
        double cycle    = g_cham / (double)(BATCH * NPTS * 2);
        double style    = -stylemse;
        double tot = diff + 0.5 * style + 0.5 * content + cycle + 0.5 * identity;
        if (out_size > 0) out[0] = (float)diff;
        if (out_size > 1) out[1] = (float)style;
        if (out_size > 2) out[2] = (float)content;
        if (out_size > 3) out[3] = (float)cycle;
        if (out_size > 4) out[4] = (float)identity;
        if (out_size > 5) out[5] = (float)tot;
        for (int i = 6; i < out_size; i++) out[i] = 0.f;
        g_acc[0] = 0.0; g_acc[1] = 0.0; g_acc[2] = 0.0; g_acc[3] = 0.0;
        g_cham = 0.0;
    }
}

// ============================================================================
// Launch (graph-capturable). Inputs:
// 0 pred_noise, 1 target_noise, 2 style_sim, 3 style_real,
// 4 content_original, 5 content_generated, 6 x_cycle, 7 x_original, 8 x_identity
// ============================================================================
extern "C" void kernel_launch(void* const* d_in, const int* in_sizes, int n_in,
                              void* d_out, int out_size) {
    (void)n_in; (void)in_sizes;
    const float* pred  = (const float*)d_in[0];
    const float* targ  = (const float*)d_in[1];
    const float* ssim  = (const float*)d_in[2];
    const float* sreal = (const float*)d_in[3];
    const float* corg  = (const float*)d_in[4];
    const float* cgen  = (const float*)d_in[5];
    const float* xcyc  = (const float*)d_in[6];
    const float* xorg  = (const float*)d_in[7];
    const float* xid   = (const float*)d_in[8];
    float* out = (float*)d_out;

    fused_kernel<<<ALL_BLOCKS, THREADS>>>(xorg, xcyc, pred, targ, ssim, sreal,
                                          corg, cgen, xid);

    final_kernel<<<FIN_BLOCKS, FIN_THREADS>>>(out, out_size);
}

// round 16
// speedup vs baseline: 5.9192x; 1.0253x over previous
#include <cuda_runtime.h>
#include <cstdint>

// ============================================================================
// Problem shapes (fixed by reference setup_inputs)
// ============================================================================
#define BATCH      4
#define NPTS       8192
#define L_DIFF     98304       // 4*8192*3
#define L_STYLE    2048        // 4*512
#define L_CONTENT  1048576     // 4*1024*256
#define L_ID       98304

// Symmetric chamfer, row-pair packed (same math as the 88.1us best):
// packed f32x2 registers hold TWO x-rows; y columns duplicated in shared.
// Block tile: 1024 rows x 256 cols. grid = 8*32*4 = 1024 chamfer + 80 MSE.
// launch_bounds(128,7): 7 blocks/SM -> 1036 concurrent -> 1.07 waves, and
// the tail wave is the short MSE blocks (placed last).
#define THREADS     128
#define RP          4                      // row-pairs per thread (8 rows)
#define XBLOCK      (THREADS * 2 * RP)     // 1024 rows per block
#define CH_I        (NPTS / XBLOCK)        // 8
#define JT          256                    // cols per block
#define CH_J        (NPTS / JT)            // 32
#define NPAIR       (JT / 2)               // 128 col-pairs
#define CH_BLOCKS   (CH_I * CH_J * BATCH)  // 1024
#define MSE_BLOCKS  80
#define ALL_BLOCKS  (CH_BLOCKS + MSE_BLOCKS)

#define FIN_BLOCKS  128
#define FIN_THREADS 256

// ============================================================================
// Scratch (device globals; zero-initialized by CUDA).
// g_enc[i] = 0xFFFFFFFF - float_bits(min d2); d2 >= 0 so every encoded value
// > 0 ==> 0 is the atomicMax identity == static init == post-reset state.
// final_kernel resets all state each call -> deterministic, no init launch.
// ============================================================================
__device__ unsigned int g_enc[2 * BATCH * NPTS];   // [dir][b][i]
__device__ double       g_acc[4];                   // diff, style, content, identity
__device__ double       g_cham;                     // sum of sqrt(min d2)
__device__ unsigned int g_ctr;                      // last-block ticket (auto-wrap)

// ============================================================================
// Packed f32x2 helpers (Blackwell; only reachable via PTX)
// ============================================================================
static __device__ __forceinline__ unsigned long long pk2(float lo, float hi) {
    unsigned long long r;
    asm("mov.b64 %0, {%1, %2};" : "=l"(r) : "f"(lo), "f"(hi));
    return r;
}
static __device__ __forceinline__ void upk2(unsigned long long v, float& lo, float& hi) {
    asm("mov.b64 {%0, %1}, %2;" : "=f"(lo), "=f"(hi) : "l"(v));
}
static __device__ __forceinline__ unsigned long long fma2(unsigned long long a,
                                                          unsigned long long b,
                                                          unsigned long long c) {
    unsigned long long d;
    asm("fma.rn.f32x2 %0, %1, %2, %3;" : "=l"(d) : "l"(a), "l"(b), "l"(c));
    return d;
}
static __device__ __forceinline__ unsigned long long mul2(unsigned long long a,
                                                          unsigned long long b) {
    unsigned long long d;
    asm("mul.rn.f32x2 %0, %1, %2;" : "=l"(d) : "l"(a), "l"(b));
    return d;
}
static __device__ __forceinline__ unsigned long long add2(unsigned long long a,
                                                          unsigned long long b) {
    unsigned long long d;
    asm("add.rn.f32x2 %0, %1, %2;" : "=l"(d) : "l"(a), "l"(b));
    return d;
}

// ============================================================================
// Symmetric chamfer tile, row-pair packed, shallow butterfly.
// rows = x_original[b]  (row-min -> cd1 / g_enc dir0)
// cols = x_cycle[b]     (col-min -> cd2 / g_enc dir1)
// Col-min reduction: 3 butterfly steps (off 16,8,4) leave lanes 0-3 holding
// the 4 distinct mod-4-class mins; stage those, merge in the col epilogue.
// ============================================================================
static __device__ __forceinline__ void chamfer_tile(
    int bid, const float* __restrict__ xo, const float* __restrict__ xc,
    unsigned long long* s_y, unsigned long long* s_part) {

    const int b  = bid >> 8;           // batch (0..3)
    const int ic = (bid >> 5) & 7;     // i-chunk (0..7)
    const int jc = bid & 31;           // j-chunk (0..31)
    const float* X = xo + (size_t)b * NPTS * 3;
    const float* Y = xc + (size_t)b * NPTS * 3;
    unsigned int* enc_row = g_enc + (size_t)b * NPTS;            // dir0
    unsigned int* enc_col = g_enc + (size_t)(BATCH + b) * NPTS;  // dir1

    const int t    = threadIdx.x;
    const int lane = t & 31;
    const int wid  = t >> 5;
    const int row0 = ic * XBLOCK + t;

    // packed (-2x) per row-PAIR: lo = row row0+2rp*T, hi = row row0+(2rp+1)*T
    unsigned long long npx[RP], npy[RP], npz[RP], rsqp[RP];
    float rminA[RP], rminB[RP];
#pragma unroll
    for (int rp = 0; rp < RP; rp++) {
        int iA = row0 + (2 * rp) * THREADS;
        int iB = row0 + (2 * rp + 1) * THREADS;
        float ax = X[3 * iA], ay = X[3 * iA + 1], az = X[3 * iA + 2];
        float bx = X[3 * iB], by = X[3 * iB + 1], bz = X[3 * iB + 2];
        npx[rp]  = pk2(-2.0f * ax, -2.0f * bx);
        npy[rp]  = pk2(-2.0f * ay, -2.0f * by);
        npz[rp]  = pk2(-2.0f * az, -2.0f * bz);
        rsqp[rp] = pk2(ax * ax + ay * ay + az * az,
                       bx * bx + by * by + bz * bz);
        rminA[rp] = 3.4e38f;
        rminB[rp] = 3.4e38f;
    }

    // y tile: per col j, 4 DUPLICATED u64: (x,x),(y,y),(z,z),(q,q) at s_y[4j..]
    const int jbase = jc * JT;
    for (int j = t; j < JT; j += THREADS) {
        const float* yj = Y + 3 * (jbase + j);
        float yx = yj[0], yy = yj[1], yz = yj[2];
        s_y[4 * j]     = pk2(yx, yx);
        s_y[4 * j + 1] = pk2(yy, yy);
        s_y[4 * j + 2] = pk2(yz, yz);
        float q = yx * yx + yy * yy + yz * yz;
        s_y[4 * j + 3] = pk2(q, q);
    }
    __syncthreads();

#pragma unroll 4
    for (int cp = 0; cp < NPAIR; cp++) {
        float cmin0 = 3.4e38f, cmin1 = 3.4e38f;
        // ---- col j0 = 2cp ----
        {
            ulonglong2 va = *(const ulonglong2*)(s_y + 8 * cp);      // x0d, y0d
            ulonglong2 vb = *(const ulonglong2*)(s_y + 8 * cp + 2);  // z0d, q0d
#pragma unroll
            for (int rp = 0; rp < RP; rp++) {
                unsigned long long s0 = mul2(npx[rp], va.x);
                s0 = fma2(npy[rp], va.y, s0);
                s0 = fma2(npz[rp], vb.x, s0);
                unsigned long long tr = add2(s0, vb.y);      // + q_j0 (dup)
                unsigned long long tc = add2(s0, rsqp[rp]);  // + (rsqA, rsqB)
                float lA, lB;
                upk2(tr, lA, lB);
                rminA[rp] = fminf(rminA[rp], lA);
                rminB[rp] = fminf(rminB[rp], lB);
                upk2(tc, lA, lB);
                cmin0 = fminf(cmin0, fminf(lA, lB));
            }
        }
        // ---- col j1 = 2cp+1 ----
        {
            ulonglong2 vc = *(const ulonglong2*)(s_y + 8 * cp + 4);  // x1d, y1d
            ulonglong2 vd = *(const ulonglong2*)(s_y + 8 * cp + 6);  // z1d, q1d
#pragma unroll
            for (int rp = 0; rp < RP; rp++) {
                unsigned long long s1 = mul2(npx[rp], vc.x);
                s1 = fma2(npy[rp], vc.y, s1);
                s1 = fma2(npz[rp], vd.x, s1);
                unsigned long long tr = add2(s1, vd.y);
                unsigned long long tc = add2(s1, rsqp[rp]);
                float lA, lB;
                upk2(tr, lA, lB);
                rminA[rp] = fminf(rminA[rp], lA);
                rminB[rp] = fminf(rminB[rp], lB);
                upk2(tc, lA, lB);
                cmin1 = fminf(cmin1, fminf(lA, lB));
            }
        }
        // shallow butterfly: 3 steps -> lanes 0-3 hold mod-4-class mins
#pragma unroll
        for (int off = 16; off > 2; off >>= 1) {
            cmin0 = fminf(cmin0, __shfl_xor_sync(0xFFFFFFFFu, cmin0, off));
            cmin1 = fminf(cmin1, __shfl_xor_sync(0xFFFFFFFFu, cmin1, off));
        }
        if (lane < 4) s_part[(wid * NPAIR + cp) * 4 + lane] = pk2(cmin0, cmin1);
    }

    // row epilogue
#pragma unroll
    for (int rp = 0; rp < RP; rp++) {
        float qA, qB;
        upk2(rsqp[rp], qA, qB);
        int iA = row0 + (2 * rp) * THREADS;
        int iB = row0 + (2 * rp + 1) * THREADS;
        float d2A = fmaxf(qA + rminA[rp], 0.0f);
        float d2B = fmaxf(qB + rminB[rp], 0.0f);
        atomicMax(enc_row + iA, 0xFFFFFFFFu - __float_as_uint(d2A));
        atomicMax(enc_row + iB, 0xFFFFFFFFu - __float_as_uint(d2B));
    }

    // col epilogue: one cp per thread; merge 4 warps x 4 class-partials
    __syncthreads();
    for (int cp = t; cp < NPAIR; cp += THREADS) {
        float m0 = 3.4e38f, m1 = 3.4e38f;
#pragma unroll
        for (int w = 0; w < 4; w++) {
#pragma unroll
            for (int g = 0; g < 4; g++) {
                float a, bb;
                upk2(s_part[(w * NPAIR + cp) * 4 + g], a, bb);
                m0 = fminf(m0, a);
                m1 = fminf(m1, bb);
            }
        }
        float q0, du, q1;
        upk2(s_y[8 * cp + 3], q0, du);
        upk2(s_y[8 * cp + 7], q1, du);
        float d20 = fmaxf(q0 + m0, 0.0f);
        float d21 = fmaxf(q1 + m1, 0.0f);
        int j = jbase + 2 * cp;
        atomicMax(enc_col + j,     0xFFFFFFFFu - __float_as_uint(d20));
        atomicMax(enc_col + j + 1, 0xFFFFFFFFu - __float_as_uint(d21));
    }
}

// ============================================================================
// MSE part (80 blocks): all 4 sums, float4-vectorized -> g_acc.
// ============================================================================
static __device__ __forceinline__ float mse_part_v4(const float4* __restrict__ a,
                                                    const float4* __restrict__ b,
                                                    int n4, int gid, int stride) {
    float s = 0.f;
    for (int i = gid; i < n4; i += stride) {
        float4 va = a[i], vb = b[i];
        float d0 = va.x - vb.x, d1 = va.y - vb.y, d2 = va.z - vb.z, d3 = va.w - vb.w;
        s += d0 * d0 + d1 * d1 + d2 * d2 + d3 * d3;
    }
    return s;
}

static __device__ __forceinline__ void mse_blocks(
    int m, const float* pred, const float* targ, const float* ssim,
    const float* sreal, const float* corg, const float* cgen,
    const float* xorg, const float* xid, float* sm) {

    const int gid    = m * THREADS + threadIdx.x;
    const int stride = MSE_BLOCKS * THREADS;

    float s[4];
    s[0] = mse_part_v4((const float4*)pred, (const float4*)targ,  L_DIFF / 4,    gid, stride);
    s[1] = mse_part_v4((const float4*)ssim, (const float4*)sreal, L_STYLE / 4,   gid, stride);
    s[2] = mse_part_v4((const float4*)corg, (const float4*)cgen,  L_CONTENT / 4, gid, stride);
    s[3] = mse_part_v4((const float4*)xorg, (const float4*)xid,   L_ID / 4,      gid, stride);

    if (threadIdx.x < 4) sm[threadIdx.x] = 0.f;
    __syncthreads();
#pragma unroll
    for (int k = 0; k < 4; k++) {
#pragma unroll
        for (int off = 16; off > 0; off >>= 1)
            s[k] += __shfl_down_sync(0xFFFFFFFFu, s[k], off);
        if ((threadIdx.x & 31) == 0) atomicAdd(&sm[k], s[k]);
    }
    __syncthreads();
    if (threadIdx.x < 4) atomicAdd(&g_acc[threadIdx.x], (double)sm[threadIdx.x]);
}

// ============================================================================
// Fused kernel: blocks [0,1024) chamfer tiles, [1024,1104) MSE (placed LAST
// so the partial tail wave consists of the short MSE blocks).
// ============================================================================
__global__ void __launch_bounds__(THREADS, 7)
fused_kernel(const float* __restrict__ xo,   const float* __restrict__ xc,
             const float* __restrict__ pred, const float* __restrict__ targ,
             const float* __restrict__ ssim, const float* __restrict__ sreal,
             const float* __restrict__ corg, const float* __restrict__ cgen,
             const float* __restrict__ xid) {
    __shared__ __align__(16) unsigned long long s_y[4 * JT];            // 8 KB
    __shared__ __align__(16) unsigned long long s_part[4 * NPAIR * 4];  // 16 KB

    const int bid = blockIdx.x;
    if (bid < CH_BLOCKS) {
        chamfer_tile(bid, xo, xc, s_y, s_part);
    } else {
        mse_blocks(bid - CH_BLOCKS, pred, targ, ssim, sreal, corg, cgen, xo, xid,
                   (float*)s_part);
    }
}

// ============================================================================
// Final kernel: sqrt-sum of g_enc + reset, last block combines + writes out
// and cleans state.
// ============================================================================
__global__ void __launch_bounds__(FIN_THREADS)
final_kernel(float* __restrict__ out, int out_size) {
    __shared__ float warpsum[FIN_THREADS / 32];
    __shared__ bool  s_last;
    const int tid  = threadIdx.x;
    const int lane = tid & 31;
    const int wid  = tid >> 5;
    const int gid  = blockIdx.x * FIN_THREADS + tid;
    const int stride = FIN_BLOCKS * FIN_THREADS;

    float cham = 0.f;
    const int total = 2 * BATCH * NPTS;
    for (int i = gid; i < total; i += stride) {
        unsigned u = g_enc[i];
        g_enc[i] = 0u;                      // clean (atomicMax identity)
        cham += sqrtf(__uint_as_float(0xFFFFFFFFu - u));
    }

#pragma unroll
    for (int off = 16; off > 0; off >>= 1)
        cham += __shfl_down_sync(0xFFFFFFFFu, cham, off);
    if (lane == 0) warpsum[wid] = cham;
    __syncthreads();
    if (wid == 0) {
        float v = (lane < FIN_THREADS / 32) ? warpsum[lane] : 0.f;
#pragma unroll
        for (int off = 4; off > 0; off >>= 1)
            v += __shfl_down_sync(0xFFFFFFFFu, v, off);
        if (lane == 0) atomicAdd(&g_cham, (double)v);
    }

    __threadfence();
    if (tid == 0) {
        unsigned t = atomicInc(&g_ctr, gridDim.x - 1);  // wraps to 0
        s_last = (t == gridDim.x - 1);
    }
    __syncthreads();
    if (s_last && tid == 0) {
        double diff     = g_acc[0] / (double)L_DIFF;
        double stylemse = g_acc[1] / (double)L_STYLE;
        double content  = g_acc[2] / (double)L_CONTENT;
        double identity = g_acc[3] / (double)L_ID;
        double cycle    = g_cham / (double)(BATCH * NPTS * 2);
        double style    = -stylemse;
        double tot = diff + 0.5 * style + 0.5 * content + cycle + 0.5 * identity;
        if (out_size > 0) out[0] = (float)diff;
        if (out_size > 1) out[1] = (float)style;
        if (out_size > 2) out[2] = (float)content;
        if (out_size > 3) out[3] = (float)cycle;
        if (out_size > 4) out[4] = (float)identity;
        if (out_size > 5) out[5] = (float)tot;
        for (int i = 6; i < out_size; i++) out[i] = 0.f;
        g_acc[0] = 0.0; g_acc[1] = 0.0; g_acc[2] = 0.0; g_acc[3] = 0.0;
        g_cham = 0.0;
    }
}

// ============================================================================
// Launch (graph-capturable). Inputs:
// 0 pred_noise, 1 target_noise, 2 style_sim, 3 style_real,
// 4 content_original, 5 content_generated, 6 x_cycle, 7 x_original, 8 x_identity
// ============================================================================
extern "C" void kernel_launch(void* const* d_in, const int* in_sizes, int n_in,
                              void* d_out, int out_size) {
    (void)n_in; (void)in_sizes;
    const float* pred  = (const float*)d_in[0];
    const float* targ  = (const float*)d_in[1];
    const float* ssim  = (const float*)d_in[2];
    const float* sreal = (const float*)d_in[3];
    const float* corg  = (const float*)d_in[4];
    const float* cgen  = (const float*)d_in[5];
    const float* xcyc  = (const float*)d_in[6];
    const float* xorg  = (const float*)d_in[7];
    const float* xid   = (const float*)d_in[8];
    float* out = (float*)d_out;

    fused_kernel<<<ALL_BLOCKS, THREADS>>>(xorg, xcyc, pred, targ, ssim, sreal,
                                          corg, cgen, xid);

    final_kernel<<<FIN_BLOCKS, FIN_THREADS>>>(out, out_size);
}